// round 15
// baseline (speedup 1.0000x reference)
#include <cuda_runtime.h>

// CRF forward log-partition. B=512, T=512, L=64.
// TIME-SPLIT + WARP-AUTONOMOUS, 4 BATCHES PER BLOCK (256 thr, 8 warps).
// grid=128 <= 148 SMs -> every block gets its own SM: uniform 2 warps/SMSP
// (eliminates R13's 2-block/1-block SM imbalance where 40 single-block SMs
// ran in the slow 1-warp/SMSP latency regime and set the kernel duration).
// warp w: batch blockIdx*4 + (w>>1), direction w&1 (0=fwd, 1=bwd).
// Inner loop per warp (unchanged from R13): lane owns tags {lane, lane+32},
// full 64-prev dot = 64 FFMA2 pair-packed, v exchange = STS.64 + __syncwarp +
// 16 broadcast LDS.128; renorm every 4 rounds (measure s==2, apply s==0,
// acc2 committed at APPLY). Combine: Z = sum_n v_fwd[n]*w_bwd[n].

#define LOG2E 1.4426950408889634f
#define LN2   0.6931471805599453f

constexpr int L    = 64;
constexpr int TT   = 512;
constexpr int HALF = 256;

static __device__ __forceinline__ float ex2f(float x) {
    float r; asm("ex2.approx.ftz.f32 %0, %1;" : "=f"(r) : "f"(x)); return r;
}
static __device__ __forceinline__ float lg2f(float x) {
    float r; asm("lg2.approx.ftz.f32 %0, %1;" : "=f"(r) : "f"(x)); return r;
}
static __device__ __forceinline__ unsigned long long pk2(float lo, float hi) {
    unsigned long long r;
    asm("mov.b64 %0, {%1, %2};" : "=l"(r) : "f"(lo), "f"(hi)); return r;
}
static __device__ __forceinline__ void upk2(unsigned long long v, float& lo, float& hi) {
    asm("mov.b64 {%0, %1}, %2;" : "=f"(lo), "=f"(hi) : "l"(v));
}
static __device__ __forceinline__ unsigned long long ffma2(
    unsigned long long a, unsigned long long b, unsigned long long c) {
    unsigned long long d;
    asm("fma.rn.f32x2 %0, %1, %2, %3;" : "=l"(d) : "l"(a), "l"(b), "l"(c)); return d;
}
static __device__ __forceinline__ unsigned long long fadd2(
    unsigned long long a, unsigned long long b) {
    unsigned long long d;
    asm("add.rn.f32x2 %0, %1, %2;" : "=l"(d) : "l"(a), "l"(b)); return d;
}

__global__ __launch_bounds__(256, 1) void crf_fwd(
    const float* __restrict__ emis,   // [B, T, L]
    const float* __restrict__ trans,  // [L, L]  trans[next*L + prev]
    float* __restrict__ out)          // [B]
{
    const int tid  = threadIdx.x;
    const int w    = tid >> 5;           // warp 0..7
    const int lane = tid & 31;
    const int dir  = w & 1;              // 0 = forward, 1 = backward
    const int b    = blockIdx.x * 4 + (w >> 1);
    const int n0   = lane, n1 = lane + 32;
    const unsigned FULL = 0xffffffffu;

    // per-warp double-buffered v: pair p = (v[p], v[p+32])
    __shared__ __align__(16) float2 v_sh[8][2][32];
    __shared__ __align__(16) float2 fin[8][32];
    __shared__ int acc_sh[8];

    // ---- E for both tags, pair-packed: fwd rows / bwd columns of exp(trans) ----
    unsigned long long E0[32], E1[32];
    if (dir == 0) {
        float ex0[64], ex1[64];
        const float4* t0 = reinterpret_cast<const float4*>(trans + n0 * L);
        const float4* t1 = reinterpret_cast<const float4*>(trans + n1 * L);
        #pragma unroll
        for (int j = 0; j < 16; j++) {
            float4 a = t0[j];
            ex0[4 * j] = __expf(a.x); ex0[4 * j + 1] = __expf(a.y);
            ex0[4 * j + 2] = __expf(a.z); ex0[4 * j + 3] = __expf(a.w);
            float4 c = t1[j];
            ex1[4 * j] = __expf(c.x); ex1[4 * j + 1] = __expf(c.y);
            ex1[4 * j + 2] = __expf(c.z); ex1[4 * j + 3] = __expf(c.w);
        }
        #pragma unroll
        for (int p = 0; p < 32; p++) {
            E0[p] = pk2(ex0[p], ex0[p + 32]);
            E1[p] = pk2(ex1[p], ex1[p + 32]);
        }
    } else {
        #pragma unroll
        for (int p = 0; p < 32; p++) {
            E0[p] = pk2(__expf(trans[p * L + n0]), __expf(trans[(p + 32) * L + n0]));
            E1[p] = pk2(__expf(trans[p * L + n1]), __expf(trans[(p + 32) * L + n1]));
        }
    }

    // ---- init state + emission stream ----
    const int dstep = dir ? -L : L;
    const float* ebase = emis + (size_t)b * (TT * L) + (dir ? 510 * L : 0) + lane;
    if (dir == 0) {
        v_sh[w][0][lane] = make_float2(0.0f, (lane == 30) ? 1.0f : 0.0f); // delta(START=62)
    } else {
        // w init = exp(trans[STOP][n]) * exp(emit[511][n])
        float es0 = __expf(trans[(L - 1) * L + n0]);
        float es1 = __expf(trans[(L - 1) * L + n1]);
        const float* e511 = emis + (size_t)b * (TT * L) + 511 * L + lane;
        float fe0 = ex2f(__ldg(e511)      * LOG2E);
        float fe1 = ex2f(__ldg(e511 + 32) * LOG2E);
        v_sh[w][0][lane] = make_float2(es0 * fe0, es1 * fe1);
    }

    // converted f for rounds j and j+1 (prefetch distance 2)
    float2 eA = make_float2(ex2f(__ldg(ebase)      * LOG2E),
                            ex2f(__ldg(ebase + 32) * LOG2E));
    float2 eB = make_float2(ex2f(__ldg(ebase + dstep)      * LOG2E),
                            ex2f(__ldg(ebase + dstep + 32) * LOG2E));
    const float* pf = ebase + 2 * dstep;

    float scale = 1.0f;
    int   pend  = 0;
    int   acc2  = 0;
    float v0 = 0.0f, v1 = 0.0f;
    int   buf = 0;
    __syncwarp();

    #pragma unroll 1
    for (int it = 0; it < HALF / 4; ++it) {
        #pragma unroll
        for (int s = 0; s < 4; ++s) {
            const int j = it * 4 + s;

            float f0 = eA.x, f1 = eA.y;
            if (s == 0) { f0 *= scale; f1 *= scale; acc2 += pend; }

            // ---- full 64-prev dot for both tags: 16 broadcast LDS.128, 64 FFMA2 ----
            const ulonglong2* vv = reinterpret_cast<const ulonglong2*>(v_sh[w][buf]);
            unsigned long long c0 = 0ull, c1 = 0ull, c2 = 0ull, c3 = 0ull;
            unsigned long long d0 = 0ull, d1 = 0ull, d2 = 0ull, d3 = 0ull;
            #pragma unroll
            for (int k = 0; k < 16; k += 2) {
                ulonglong2 qa = vv[k];       // pairs 2k, 2k+1
                ulonglong2 qb = vv[k + 1];   // pairs 2k+2, 2k+3
                c0 = ffma2(qa.x, E0[2 * k],     c0);
                c1 = ffma2(qa.y, E0[2 * k + 1], c1);
                c2 = ffma2(qb.x, E0[2 * k + 2], c2);
                c3 = ffma2(qb.y, E0[2 * k + 3], c3);
                d0 = ffma2(qa.x, E1[2 * k],     d0);
                d1 = ffma2(qa.y, E1[2 * k + 1], d1);
                d2 = ffma2(qb.x, E1[2 * k + 2], d2);
                d3 = ffma2(qb.y, E1[2 * k + 3], d3);
            }
            float s0, s1;
            { float lo, hi; upk2(fadd2(fadd2(c0, c1), fadd2(c2, c3)), lo, hi); s0 = lo + hi; }
            { float lo, hi; upk2(fadd2(fadd2(d0, d1), fadd2(d2, d3)), lo, hi); s1 = lo + hi; }

            v0 = s0 * f0;
            v1 = s1 * f1;

            v_sh[w][buf ^ 1][lane] = make_float2(v0, v1);

            if (s == 2) {
                // measure max; applied at next s==0 (acc2 committed on APPLY,
                // final measured-but-unapplied scale correctly discarded)
                float wm = fmaxf(v0, v1);
                #pragma unroll
                for (int o = 16; o >= 1; o >>= 1)
                    wm = fmaxf(wm, __shfl_xor_sync(FULL, wm, o));
                int ei = (int)((__float_as_uint(wm) >> 23) & 0xff);
                scale = __uint_as_float((unsigned)(253 - ei) << 23); // 2^(126-ei)
                pend  = ei - 126;
            }

            // prefetch f for round j+2 (bwd masks rounds > 254 -> f = 1)
            {
                float r0 = __ldg(pf);
                float r1 = __ldg(pf + 32);
                pf += dstep;
                if (dir && (j + 2 > 254)) { r0 = 0.0f; r1 = 0.0f; }
                eA = eB;
                eB = make_float2(ex2f(r0 * LOG2E), ex2f(r1 * LOG2E));
            }

            __syncwarp();
            buf ^= 1;
        }
    }

    // ---- combine per batch: Z = sum_n v[n]*w[n]; log2-scales add ----
    fin[w][lane] = make_float2(v0, v1);
    if (lane == 0) acc_sh[w] = acc2;
    __syncthreads();
    if ((w & 1) == 0) {                     // even warps combine their pair
        float2 a = fin[w][lane];
        float2 c = fin[w + 1][lane];
        float p = a.x * c.x + a.y * c.y;
        #pragma unroll
        for (int o = 16; o >= 1; o >>= 1) p += __shfl_xor_sync(FULL, p, o);
        if (lane == 0)
            out[b] = (lg2f(p) + (float)(acc_sh[w] + acc_sh[w + 1])) * LN2;
    }
}

extern "C" void kernel_launch(void* const* d_in, const int* in_sizes, int n_in,
                              void* d_out, int out_size) {
    const float* emis  = (const float*)d_in[0];   // [B, T, L] float32
    const float* trans = (const float*)d_in[1];   // [L, L] float32
    float* out = (float*)d_out;                   // [B] float32
    int B = in_sizes[0] / (TT * L);
    crf_fwd<<<B / 4, 256>>>(emis, trans, out);
}